// round 11
// baseline (speedup 1.0000x reference)
#include <cuda_runtime.h>
#include <cstdint>
#include <cstddef>

// ---------------------------------------------------------------------------
// Problem constants
// ---------------------------------------------------------------------------
#define B_SZ   8192
#define D_IN   19200
#define D1     512
#define D2     256
#define D_PW   128
#define N_PW   25
#define N_DRUG 1448

// ---------------------------------------------------------------------------
// GEMM tiling: 128x256 CTA tile, 8 warps of 64x64, BK=32, 4-stage cp.async
// ---------------------------------------------------------------------------
#define BM 128
#define BN 256
#define BK 32
#define STAGES 4
#define ASTR 36    // padded A smem stride (floats): conflict-free frag loads
#define BSTR 264   // padded B smem stride (floats): tg*264+g mod 32 distinct
#define SMEM_FLOATS (STAGES * (BM * ASTR + BK * BSTR))
#define SMEM_BYTES  (SMEM_FLOATS * 4)   // 208,896 B

// Head kernel
#define CHUNK 64
#define WSTR 260
#define HEAD_SMEM_BYTES ((128 * WSTR + CHUNK * 256 + 32) * 4 + CHUNK * 8 + 64)

// Scratch (allocation-free rule: __device__ globals)
__device__ float g_h1[B_SZ * D1];       // relu(x@W1+b1)
__device__ float g_h2[B_SZ * D2];       // relu(h1@W2+b2)
__device__ float g_w1r[D_IN * D1];      // W1 pre-rounded to tf32 (rna)
__device__ float g_w2r[D1 * D2];        // W2 pre-rounded to tf32 (rna)
__device__ int   g_idx64;               // 1 if drug_indices buffer is int64
__device__ int   g_cnt[N_PW];           // per-pathway sample counts
__device__ int   g_bucket[N_PW][B_SZ];  // per-pathway sample lists

// ---------------------------------------------------------------------------
// PTX helpers
// ---------------------------------------------------------------------------
__device__ __forceinline__ uint32_t f2tf32(float x) {
    uint32_t r;
    asm("cvt.rna.tf32.f32 %0, %1;" : "=r"(r) : "f"(x));
    return r;
}

__device__ __forceinline__ void cp16(float* s, const float* g) {
    uint32_t sa = (uint32_t)__cvta_generic_to_shared(s);
    asm volatile("cp.async.cg.shared.global [%0], [%1], 16;" :: "r"(sa), "l"(g));
}
__device__ __forceinline__ void cp_commit() {
    asm volatile("cp.async.commit_group;" ::: "memory");
}
__device__ __forceinline__ void cp_waitN() {
    asm volatile("cp.async.wait_group %0;" :: "n"(STAGES - 2) : "memory");
}

__device__ __forceinline__ void mma8(float* c, const uint32_t* a, const uint32_t* b) {
    asm volatile(
        "mma.sync.aligned.m16n8k8.row.col.f32.tf32.tf32.f32 "
        "{%0,%1,%2,%3}, {%4,%5,%6,%7}, {%8,%9}, {%0,%1,%2,%3};"
        : "+f"(c[0]), "+f"(c[1]), "+f"(c[2]), "+f"(c[3])
        : "r"(a[0]), "r"(a[1]), "r"(a[2]), "r"(a[3]),
          "r"(b[0]), "r"(b[1]));
}

// ---------------------------------------------------------------------------
// drug_indices dtype detection (int64 high words are all zero; int32 is not)
// ---------------------------------------------------------------------------
__global__ void detect_idx_dtype_kernel(const int* __restrict__ di32) {
    __shared__ int s;
    if (threadIdx.x == 0) s = 0;
    __syncthreads();
    int acc = 0;
    for (int i = threadIdx.x; i < B_SZ / 2; i += blockDim.x)
        acc |= di32[2 * i + 1];
    if (acc) atomicOr(&s, 1);
    __syncthreads();
    if (threadIdx.x == 0) g_idx64 = (s == 0) ? 1 : 0;
}

// ---------------------------------------------------------------------------
// Pathway bucketing (re-run every launch: graph-replay safe; each out[b]
// is written exactly once -> deterministic results regardless of ordering)
// ---------------------------------------------------------------------------
__global__ void bucket_zero_kernel() {
    if (threadIdx.x < N_PW) g_cnt[threadIdx.x] = 0;
}
__global__ void bucket_fill_kernel(const int* __restrict__ di32,
                                   const int* __restrict__ drug_pw) {
    int b = blockIdx.x * blockDim.x + threadIdx.x;
    if (b >= B_SZ) return;
    int d = g_idx64 ? di32[2 * b] : di32[b];
    d = min(max(d, 0), N_DRUG - 1);
    int p = drug_pw[d];
    p = min(max(p, 0), N_PW - 1);
    int pos = atomicAdd(&g_cnt[p], 1);
    g_bucket[p][pos] = b;
}

// ---------------------------------------------------------------------------
// Elementwise round-to-tf32 (rna) copy. n % 1024 == 0 for both weights.
// After this, HW truncation inside mma.sync == identity -> no in-loop cvt.
// ---------------------------------------------------------------------------
__global__ void round_tf32_kernel(const float* __restrict__ src,
                                  float* __restrict__ dst, int n4) {
    int i = blockIdx.x * blockDim.x + threadIdx.x;
    if (i >= n4) return;
    float4 v = reinterpret_cast<const float4*>(src)[i];
    v.x = __uint_as_float(f2tf32(v.x));
    v.y = __uint_as_float(f2tf32(v.y));
    v.z = __uint_as_float(f2tf32(v.z));
    v.w = __uint_as_float(f2tf32(v.w));
    reinterpret_cast<float4*>(dst)[i] = v;
}

// ---------------------------------------------------------------------------
// Fused GEMM + bias + ReLU:  C[M,N] = relu(A[M,K] @ B[K,N] + bias[N])
// TF32 mma.sync m16n8k8, warp tile 64x64, 4-stage cp.async, 1 sync/iter.
// B must be pre-rounded to tf32 (raw fragment bits); A cvt.rna'd in-loop.
// Requires M%128==0, N%256==0, K%32==0.
// ---------------------------------------------------------------------------
__global__ void __launch_bounds__(256) gemm_bias_relu_kernel(
    const float* __restrict__ A, const float* __restrict__ Bm,
    const float* __restrict__ bias, float* __restrict__ C,
    int M, int N, int K)
{
    extern __shared__ float smem[];
    float* sA = smem;                        // [STAGES][BM][ASTR]
    float* sB = smem + STAGES * BM * ASTR;   // [STAGES][BK][BSTR]

    const int tid  = threadIdx.x;
    const int warp = tid >> 5;
    const int lane = tid & 31;
    const int m0 = blockIdx.x * BM;
    const int n0 = blockIdx.y * BN;
    const int wm = (warp >> 2) * 64;   // 2 M-warps
    const int wn = (warp & 3) * 64;    // 4 N-warps
    const int g  = lane >> 2;          // 0..7
    const int tg = lane & 3;           // 0..3
    const int KT = K / BK;

    float acc[4][8][4];
    #pragma unroll
    for (int i = 0; i < 4; i++)
        #pragma unroll
        for (int j = 0; j < 8; j++)
            #pragma unroll
            for (int k = 0; k < 4; k++) acc[i][j][k] = 0.f;

    // cp.async lane assignments
    const int ar = tid >> 3;          // 0..31 (A row), 4 passes of 32 rows
    const int ac = (tid & 7) * 4;     // A col float4
    const int br = tid >> 6;          // 0..3  (B row), 8 passes of 4 rows
    const int bc = (tid & 63) * 4;    // B col float4 (0..252)

    auto load_tile = [&](int stage, int kt) {
        const float* Ag = A + (size_t)m0 * K + (size_t)kt * BK;
        float* sAs = sA + stage * BM * ASTR;
        #pragma unroll
        for (int i = 0; i < 4; i++) {
            int r = ar + i * 32;
            cp16(sAs + r * ASTR + ac, Ag + (size_t)r * K + ac);
        }
        const float* Bg = Bm + (size_t)(kt * BK) * N + n0;
        float* sBs = sB + stage * BK * BSTR;
        #pragma unroll
        for (int i = 0; i < 8; i++) {
            int r = br + i * 4;
            cp16(sBs + r * BSTR + bc, Bg + (size_t)r * N + bc);
        }
    };

    auto compute_tile = [&](int stage) {
        const float* sAs = sA + stage * BM * ASTR + wm * ASTR;
        const float* sBs = sB + stage * BK * BSTR + wn;
        #pragma unroll
        for (int kk = 0; kk < 4; kk++) {
            const int k = kk * 8;
            uint32_t aF[4][4];
            uint32_t bF[8][2];
            #pragma unroll
            for (int mt = 0; mt < 4; mt++) {
                const float* ap = sAs + (mt * 16) * ASTR + k;
                aF[mt][0] = f2tf32(ap[g * ASTR + tg]);
                aF[mt][1] = f2tf32(ap[(g + 8) * ASTR + tg]);
                aF[mt][2] = f2tf32(ap[g * ASTR + tg + 4]);
                aF[mt][3] = f2tf32(ap[(g + 8) * ASTR + tg + 4]);
            }
            #pragma unroll
            for (int nt = 0; nt < 8; nt++) {
                // B pre-rounded to tf32: raw bits, no cvt needed
                const float* bp_ = sBs + (k + tg) * BSTR + nt * 8 + g;
                bF[nt][0] = __float_as_uint(bp_[0]);
                bF[nt][1] = __float_as_uint(bp_[4 * BSTR]);
            }
            #pragma unroll
            for (int mt = 0; mt < 4; mt++)
                #pragma unroll
                for (int nt = 0; nt < 8; nt++)
                    mma8(acc[mt][nt], aF[mt], bF[nt]);
        }
    };

    // Prologue: fill STAGES-1 stages
    #pragma unroll
    for (int s = 0; s < STAGES - 1; s++) {
        if (s < KT) load_tile(s, s);
        cp_commit();
    }

    // Mainloop: ONE barrier per iter. Write target (kt+STAGES-1) is >= 2
    // stages ahead of the stage being read; the top barrier of the iter in
    // which a slot is rewritten orders it after every warp's read of it.
    for (int kt = 0; kt < KT; kt++) {
        cp_waitN();
        __syncthreads();
        int nk = kt + STAGES - 1;
        if (nk < KT) load_tile(nk % STAGES, nk);
        cp_commit();                  // empty group on tail iters keeps
        compute_tile(kt % STAGES);    // wait_group accounting correct
    }

    // Epilogue: bias + relu, float2 stores
    #pragma unroll
    for (int mt = 0; mt < 4; mt++) {
        #pragma unroll
        for (int nt = 0; nt < 8; nt++) {
            int row = m0 + wm + mt * 16 + g;
            int col = n0 + wn + nt * 8 + 2 * tg;
            float bv0 = bias[col];
            float bv1 = bias[col + 1];
            float2 v0, v1;
            v0.x = fmaxf(acc[mt][nt][0] + bv0, 0.f);
            v0.y = fmaxf(acc[mt][nt][1] + bv1, 0.f);
            v1.x = fmaxf(acc[mt][nt][2] + bv0, 0.f);
            v1.y = fmaxf(acc[mt][nt][3] + bv1, 0.f);
            *reinterpret_cast<float2*>(C + (size_t)row * N + col)       = v0;
            *reinterpret_cast<float2*>(C + (size_t)(row + 8) * N + col) = v1;
        }
    }
}

// ---------------------------------------------------------------------------
// Pathway-grouped head (unchanged from R5; ~25us, L2-resident)
// ---------------------------------------------------------------------------
__global__ void __launch_bounds__(256) head_kernel(
    const float* __restrict__ h2, const float* __restrict__ Wp,
    const float* __restrict__ bp, const float* __restrict__ Wd,
    const float* __restrict__ bd, const int* __restrict__ di32,
    float* __restrict__ out)
{
    const int p = blockIdx.y;
    const int c = blockIdx.x;
    const int n = g_cnt[p];
    if (c * CHUNK >= n) return;
    const int nly = min(CHUNK, n - c * CHUNK);

    extern __shared__ float hsm_raw[];
    float* ws  = hsm_raw;                       // [128][WSTR]
    float* hsm = ws + 128 * WSTR;               // [CHUNK][256]
    float* red = hsm + CHUNK * 256;             // [8][4]
    int*   sb  = (int*)(red + 32);              // [CHUNK]
    int*   sd  = sb + CHUNK;                    // [CHUNK]

    const int tid = threadIdx.x;

    if (tid < CHUNK) {
        if (tid < nly) {
            int b = g_bucket[p][c * CHUNK + tid];
            int d = g_idx64 ? di32[2 * b] : di32[b];
            d = min(max(d, 0), N_DRUG - 1);
            sb[tid] = b;
            sd[tid] = d;
        } else {
            sb[tid] = 0;
            sd[tid] = 0;
        }
    }

    {
        const float4* Wp4 = reinterpret_cast<const float4*>(Wp + (size_t)p * D_PW * 256);
        for (int idx = tid; idx < 128 * 64; idx += 256) {
            int r = idx >> 6, cc = idx & 63;
            float4 v = Wp4[idx];
            *reinterpret_cast<float4*>(ws + r * WSTR + cc * 4) = v;
        }
    }
    __syncthreads();

    for (int idx = tid; idx < nly * 64; idx += 256) {
        int s = idx >> 6, cc = idx & 63;
        float4 v = reinterpret_cast<const float4*>(h2 + (size_t)sb[s] * 256)[cc];
        *reinterpret_cast<float4*>(hsm + s * 256 + cc * 4) = v;
    }
    __syncthreads();

    const int kk  = tid & 127;
    const int grp = tid >> 7;
    const int wrp = tid >> 5;
    const int lane = tid & 31;
    const float bpv = bp[p * D_PW + kk];
    const float4* wrow = reinterpret_cast<const float4*>(ws + kk * WSTR);

    for (int i0 = 0; i0 < 32; i0 += 4) {
        int s[4];
        const float4* hr[4];
        #pragma unroll
        for (int u = 0; u < 4; u++) {
            s[u] = 2 * (i0 + u) + grp;
            hr[u] = reinterpret_cast<const float4*>(hsm + s[u] * 256);
        }
        float acc0 = 0.f, acc1 = 0.f, acc2 = 0.f, acc3 = 0.f;
        #pragma unroll 8
        for (int j = 0; j < 64; j++) {
            float4 w4 = wrow[j];
            float4 a = hr[0][j], b2 = hr[1][j], c2 = hr[2][j], d2 = hr[3][j];
            acc0 += w4.x * a.x + w4.y * a.y + w4.z * a.z + w4.w * a.w;
            acc1 += w4.x * b2.x + w4.y * b2.y + w4.z * b2.z + w4.w * b2.w;
            acc2 += w4.x * c2.x + w4.y * c2.y + w4.z * c2.z + w4.w * c2.w;
            acc3 += w4.x * d2.x + w4.y * d2.y + w4.z * d2.z + w4.w * d2.w;
        }
        float v[4] = {acc0, acc1, acc2, acc3};
        #pragma unroll
        for (int u = 0; u < 4; u++) {
            float a = fmaxf(v[u] + bpv, 0.f) * Wd[(size_t)sd[s[u]] * D_PW + kk];
            #pragma unroll
            for (int o = 16; o > 0; o >>= 1)
                a += __shfl_xor_sync(0xffffffffu, a, o);
            if (lane == 0) red[wrp * 4 + u] = a;
        }
        __syncthreads();
        if (tid < 8) {
            int gg = tid >> 2, u = tid & 3;
            int ss = 2 * (i0 + u) + gg;
            if (ss < nly) {
                float t = red[(gg * 4 + 0) * 4 + u] + red[(gg * 4 + 1) * 4 + u]
                        + red[(gg * 4 + 2) * 4 + u] + red[(gg * 4 + 3) * 4 + u];
                out[sb[ss]] = t + bd[sd[ss]];
            }
        }
        __syncthreads();
    }
}

// ---------------------------------------------------------------------------
// Launch
// ---------------------------------------------------------------------------
extern "C" void kernel_launch(void* const* d_in, const int* in_sizes, int n_in,
                              void* d_out, int out_size)
{
    const float* x   = (const float*)d_in[0];
    const float* W1  = (const float*)d_in[1];
    const float* b1  = (const float*)d_in[2];
    const float* W2  = (const float*)d_in[3];
    const float* b2  = (const float*)d_in[4];
    const float* Wp  = (const float*)d_in[5];
    const float* bp  = (const float*)d_in[6];
    const float* Wd  = (const float*)d_in[7];
    const float* bd  = (const float*)d_in[8];
    const int*   di  = (const int*)d_in[9];
    const int*   dpw = (const int*)d_in[10];
    float* out = (float*)d_out;

    void *p1, *p2, *p3, *p4;
    cudaGetSymbolAddress(&p1, g_h1);
    cudaGetSymbolAddress(&p2, g_h2);
    cudaGetSymbolAddress(&p3, g_w1r);
    cudaGetSymbolAddress(&p4, g_w2r);
    float* h1  = (float*)p1;
    float* h2  = (float*)p2;
    float* w1r = (float*)p3;
    float* w2r = (float*)p4;

    cudaFuncSetAttribute(gemm_bias_relu_kernel,
                         cudaFuncAttributeMaxDynamicSharedMemorySize, SMEM_BYTES);
    cudaFuncSetAttribute(head_kernel,
                         cudaFuncAttributeMaxDynamicSharedMemorySize, HEAD_SMEM_BYTES);

    // Index dtype + pathway buckets (graph-replay-safe)
    detect_idx_dtype_kernel<<<1, 256>>>(di);
    bucket_zero_kernel<<<1, 32>>>();
    bucket_fill_kernel<<<B_SZ / 256, 256>>>(di, dpw);

    // Pre-round weights to tf32 (rna) so GEMM B-fragments skip in-loop cvt
    {
        int n4 = (D_IN * D1) / 4;
        round_tf32_kernel<<<(n4 + 255) / 256, 256>>>(W1, w1r, n4);
        n4 = (D1 * D2) / 4;
        round_tf32_kernel<<<(n4 + 255) / 256, 256>>>(W2, w2r, n4);
    }

    // GEMM1: [8192,19200] @ [19200,512] -> h1
    gemm_bias_relu_kernel<<<dim3(B_SZ / BM, D1 / BN), 256, SMEM_BYTES>>>(
        x, w1r, b1, h1, B_SZ, D1, D_IN);
    // GEMM2: [8192,512] @ [512,256] -> h2
    gemm_bias_relu_kernel<<<dim3(B_SZ / BM, D2 / BN), 256, SMEM_BYTES>>>(
        h1, w2r, b2, h2, B_SZ, D2, D1);
    // Pathway-grouped head
    head_kernel<<<dim3((B_SZ + CHUNK - 1) / CHUNK, N_PW), 256, HEAD_SMEM_BYTES>>>(
        h2, Wp, bp, Wd, bd, di, out);
}

// round 12
// speedup vs baseline: 1.5569x; 1.5569x over previous
#include <cuda_runtime.h>
#include <cstdint>
#include <cstddef>

// ---------------------------------------------------------------------------
// Problem constants
// ---------------------------------------------------------------------------
#define B_SZ   8192
#define D_IN   19200
#define D1     512
#define D2     256
#define D_PW   128
#define N_PW   25
#define N_DRUG 1448

// ---------------------------------------------------------------------------
// GEMM tiling: 128x256 CTA tile, 16 warps of 32x64, BK=32, 3-stage cp.async
// (R5-proven loop skeleton: double barrier per iter, wait_group 1)
// ---------------------------------------------------------------------------
#define BM 128
#define BN 256
#define BK 32
#define STAGES 3
#define NTHR 512
#define ASTR 36    // padded A smem stride (floats): conflict-free frag loads
#define BSTR 264   // padded B smem stride (floats): tg*264+g mod 32 distinct
#define SMEM_FLOATS (STAGES * (BM * ASTR + BK * BSTR))
#define SMEM_BYTES  (SMEM_FLOATS * 4)   // 156,672 B

// Head kernel
#define CHUNK 64
#define WSTR 260
#define HEAD_SMEM_BYTES ((128 * WSTR + CHUNK * 256 + 32) * 4 + CHUNK * 8 + 64)

// Scratch (allocation-free rule: __device__ globals)
__device__ float g_h1[B_SZ * D1];       // relu(x@W1+b1)
__device__ float g_h2[B_SZ * D2];       // relu(h1@W2+b2)
__device__ float g_w1r[D_IN * D1];      // W1 pre-rounded to tf32 (rna)
__device__ float g_w2r[D1 * D2];        // W2 pre-rounded to tf32 (rna)
__device__ int   g_idx64;               // 1 if drug_indices buffer is int64
__device__ int   g_cnt[N_PW];           // per-pathway sample counts
__device__ int   g_bucket[N_PW][B_SZ];  // per-pathway sample lists

// ---------------------------------------------------------------------------
// PTX helpers
// ---------------------------------------------------------------------------
__device__ __forceinline__ uint32_t f2tf32(float x) {
    uint32_t r;
    asm("cvt.rna.tf32.f32 %0, %1;" : "=r"(r) : "f"(x));
    return r;
}

__device__ __forceinline__ void cp16(float* s, const float* g) {
    uint32_t sa = (uint32_t)__cvta_generic_to_shared(s);
    asm volatile("cp.async.cg.shared.global [%0], [%1], 16;" :: "r"(sa), "l"(g));
}
__device__ __forceinline__ void cp_commit() {
    asm volatile("cp.async.commit_group;" ::: "memory");
}
__device__ __forceinline__ void cp_wait1() {
    asm volatile("cp.async.wait_group 1;" ::: "memory");
}

__device__ __forceinline__ void mma8(float* c, const uint32_t* a, const uint32_t* b) {
    asm volatile(
        "mma.sync.aligned.m16n8k8.row.col.f32.tf32.tf32.f32 "
        "{%0,%1,%2,%3}, {%4,%5,%6,%7}, {%8,%9}, {%0,%1,%2,%3};"
        : "+f"(c[0]), "+f"(c[1]), "+f"(c[2]), "+f"(c[3])
        : "r"(a[0]), "r"(a[1]), "r"(a[2]), "r"(a[3]),
          "r"(b[0]), "r"(b[1]));
}

// ---------------------------------------------------------------------------
// drug_indices dtype detection (int64 high words are all zero; int32 is not)
// ---------------------------------------------------------------------------
__global__ void detect_idx_dtype_kernel(const int* __restrict__ di32) {
    __shared__ int s;
    if (threadIdx.x == 0) s = 0;
    __syncthreads();
    int acc = 0;
    for (int i = threadIdx.x; i < B_SZ / 2; i += blockDim.x)
        acc |= di32[2 * i + 1];
    if (acc) atomicOr(&s, 1);
    __syncthreads();
    if (threadIdx.x == 0) g_idx64 = (s == 0) ? 1 : 0;
}

// ---------------------------------------------------------------------------
// Pathway bucketing (re-run every launch: graph-replay safe; each out[b]
// is written exactly once -> deterministic results regardless of ordering)
// ---------------------------------------------------------------------------
__global__ void bucket_zero_kernel() {
    if (threadIdx.x < N_PW) g_cnt[threadIdx.x] = 0;
}
__global__ void bucket_fill_kernel(const int* __restrict__ di32,
                                   const int* __restrict__ drug_pw) {
    int b = blockIdx.x * blockDim.x + threadIdx.x;
    if (b >= B_SZ) return;
    int d = g_idx64 ? di32[2 * b] : di32[b];
    d = min(max(d, 0), N_DRUG - 1);
    int p = drug_pw[d];
    p = min(max(p, 0), N_PW - 1);
    int pos = atomicAdd(&g_cnt[p], 1);
    g_bucket[p][pos] = b;
}

// ---------------------------------------------------------------------------
// Elementwise round-to-tf32 (rna) copy. HW truncation inside mma.sync of an
// already-rounded value is the identity -> B fragments skip in-loop cvt,
// bit-identical to cvt.rna in the loop.
// ---------------------------------------------------------------------------
__global__ void round_tf32_kernel(const float* __restrict__ src,
                                  float* __restrict__ dst, int n4) {
    int i = blockIdx.x * blockDim.x + threadIdx.x;
    if (i >= n4) return;
    float4 v = reinterpret_cast<const float4*>(src)[i];
    v.x = __uint_as_float(f2tf32(v.x));
    v.y = __uint_as_float(f2tf32(v.y));
    v.z = __uint_as_float(f2tf32(v.z));
    v.w = __uint_as_float(f2tf32(v.w));
    reinterpret_cast<float4*>(dst)[i] = v;
}

// ---------------------------------------------------------------------------
// Fused GEMM + bias + ReLU:  C[M,N] = relu(A[M,K] @ B[K,N] + bias[N])
// TF32 mma.sync m16n8k8, 16 warps of 32x64, 3-stage cp.async pipeline,
// R5-proven double-barrier loop. Requires M%128==0, N%256==0, K%32==0.
// ---------------------------------------------------------------------------
__global__ void __launch_bounds__(NTHR, 1) gemm_bias_relu_kernel(
    const float* __restrict__ A, const float* __restrict__ Bm,
    const float* __restrict__ bias, float* __restrict__ C,
    int M, int N, int K)
{
    extern __shared__ float smem[];
    float* sA = smem;                        // [STAGES][BM][ASTR]
    float* sB = smem + STAGES * BM * ASTR;   // [STAGES][BK][BSTR]

    const int tid  = threadIdx.x;
    const int warp = tid >> 5;
    const int lane = tid & 31;
    const int m0 = blockIdx.x * BM;
    const int n0 = blockIdx.y * BN;
    const int wm = (warp >> 2) * 32;   // 4 M-warps of 32 rows
    const int wn = (warp & 3) * 64;    // 4 N-warps of 64 cols
    const int g  = lane >> 2;          // 0..7
    const int tg = lane & 3;           // 0..3
    const int KT = K / BK;

    float acc[2][8][4];
    #pragma unroll
    for (int i = 0; i < 2; i++)
        #pragma unroll
        for (int j = 0; j < 8; j++)
            #pragma unroll
            for (int k = 0; k < 4; k++) acc[i][j][k] = 0.f;

    // cp.async lane assignments (512 threads)
    const int ar = tid >> 3;          // 0..63 (A row), 2 passes of 64 rows
    const int ac = (tid & 7) * 4;     // A col float4
    const int br = tid >> 6;          // 0..7  (B row), 4 passes of 8 rows
    const int bc = (tid & 63) * 4;    // B col float4 (0..252)

    auto load_tile = [&](int stage, int kt) {
        const float* Ag = A + (size_t)m0 * K + (size_t)kt * BK;
        float* sAs = sA + stage * BM * ASTR;
        #pragma unroll
        for (int i = 0; i < 2; i++) {
            int r = ar + i * 64;
            cp16(sAs + r * ASTR + ac, Ag + (size_t)r * K + ac);
        }
        const float* Bg = Bm + (size_t)(kt * BK) * N + n0;
        float* sBs = sB + stage * BK * BSTR;
        #pragma unroll
        for (int i = 0; i < 4; i++) {
            int r = br + i * 8;
            cp16(sBs + r * BSTR + bc, Bg + (size_t)r * N + bc);
        }
    };

    auto compute_tile = [&](int stage) {
        const float* sAs = sA + stage * BM * ASTR + wm * ASTR;
        const float* sBs = sB + stage * BK * BSTR + wn;
        #pragma unroll
        for (int kk = 0; kk < 4; kk++) {
            const int k = kk * 8;
            uint32_t aF[2][4];
            uint32_t bF[8][2];
            #pragma unroll
            for (int mt = 0; mt < 2; mt++) {
                const float* ap = sAs + (mt * 16) * ASTR + k;
                aF[mt][0] = f2tf32(ap[g * ASTR + tg]);
                aF[mt][1] = f2tf32(ap[(g + 8) * ASTR + tg]);
                aF[mt][2] = f2tf32(ap[g * ASTR + tg + 4]);
                aF[mt][3] = f2tf32(ap[(g + 8) * ASTR + tg + 4]);
            }
            #pragma unroll
            for (int nt = 0; nt < 8; nt++) {
                // B pre-rounded to tf32: raw fragment bits, no cvt
                const float* bp_ = sBs + (k + tg) * BSTR + nt * 8 + g;
                bF[nt][0] = __float_as_uint(bp_[0]);
                bF[nt][1] = __float_as_uint(bp_[4 * BSTR]);
            }
            #pragma unroll
            for (int mt = 0; mt < 2; mt++)
                #pragma unroll
                for (int nt = 0; nt < 8; nt++)
                    mma8(acc[mt][nt], aF[mt], bF[nt]);
        }
    };

    // Prologue: fill STAGES-1 stages
    load_tile(0, 0);
    cp_commit();
    if (KT > 1) load_tile(1, 1);
    cp_commit();

    // Mainloop (R5-proven): wait; sync; load next; commit; compute; sync
    for (int kt = 0; kt < KT; kt++) {
        cp_wait1();
        __syncthreads();
        int nk = kt + STAGES - 1;
        if (nk < KT) load_tile(nk % STAGES, nk);
        cp_commit();
        compute_tile(kt % STAGES);
        __syncthreads();
    }

    // Epilogue: bias + relu, float2 stores
    #pragma unroll
    for (int mt = 0; mt < 2; mt++) {
        #pragma unroll
        for (int nt = 0; nt < 8; nt++) {
            int row = m0 + wm + mt * 16 + g;
            int col = n0 + wn + nt * 8 + 2 * tg;
            float bv0 = bias[col];
            float bv1 = bias[col + 1];
            float2 v0, v1;
            v0.x = fmaxf(acc[mt][nt][0] + bv0, 0.f);
            v0.y = fmaxf(acc[mt][nt][1] + bv1, 0.f);
            v1.x = fmaxf(acc[mt][nt][2] + bv0, 0.f);
            v1.y = fmaxf(acc[mt][nt][3] + bv1, 0.f);
            *reinterpret_cast<float2*>(C + (size_t)row * N + col)       = v0;
            *reinterpret_cast<float2*>(C + (size_t)(row + 8) * N + col) = v1;
        }
    }
}

// ---------------------------------------------------------------------------
// Pathway-grouped head (unchanged; ~25us)
// ---------------------------------------------------------------------------
__global__ void __launch_bounds__(256) head_kernel(
    const float* __restrict__ h2, const float* __restrict__ Wp,
    const float* __restrict__ bp, const float* __restrict__ Wd,
    const float* __restrict__ bd, const int* __restrict__ di32,
    float* __restrict__ out)
{
    const int p = blockIdx.y;
    const int c = blockIdx.x;
    const int n = g_cnt[p];
    if (c * CHUNK >= n) return;
    const int nly = min(CHUNK, n - c * CHUNK);

    extern __shared__ float hsm_raw[];
    float* ws  = hsm_raw;                       // [128][WSTR]
    float* hsm = ws + 128 * WSTR;               // [CHUNK][256]
    float* red = hsm + CHUNK * 256;             // [8][4]
    int*   sb  = (int*)(red + 32);              // [CHUNK]
    int*   sd  = sb + CHUNK;                    // [CHUNK]

    const int tid = threadIdx.x;

    if (tid < CHUNK) {
        if (tid < nly) {
            int b = g_bucket[p][c * CHUNK + tid];
            int d = g_idx64 ? di32[2 * b] : di32[b];
            d = min(max(d, 0), N_DRUG - 1);
            sb[tid] = b;
            sd[tid] = d;
        } else {
            sb[tid] = 0;
            sd[tid] = 0;
        }
    }

    {
        const float4* Wp4 = reinterpret_cast<const float4*>(Wp + (size_t)p * D_PW * 256);
        for (int idx = tid; idx < 128 * 64; idx += 256) {
            int r = idx >> 6, cc = idx & 63;
            float4 v = Wp4[idx];
            *reinterpret_cast<float4*>(ws + r * WSTR + cc * 4) = v;
        }
    }
    __syncthreads();

    for (int idx = tid; idx < nly * 64; idx += 256) {
        int s = idx >> 6, cc = idx & 63;
        float4 v = reinterpret_cast<const float4*>(h2 + (size_t)sb[s] * 256)[cc];
        *reinterpret_cast<float4*>(hsm + s * 256 + cc * 4) = v;
    }
    __syncthreads();

    const int kk  = tid & 127;
    const int grp = tid >> 7;
    const int wrp = tid >> 5;
    const int lane = tid & 31;
    const float bpv = bp[p * D_PW + kk];
    const float4* wrow = reinterpret_cast<const float4*>(ws + kk * WSTR);

    for (int i0 = 0; i0 < 32; i0 += 4) {
        int s[4];
        const float4* hr[4];
        #pragma unroll
        for (int u = 0; u < 4; u++) {
            s[u] = 2 * (i0 + u) + grp;
            hr[u] = reinterpret_cast<const float4*>(hsm + s[u] * 256);
        }
        float acc0 = 0.f, acc1 = 0.f, acc2 = 0.f, acc3 = 0.f;
        #pragma unroll 8
        for (int j = 0; j < 64; j++) {
            float4 w4 = wrow[j];
            float4 a = hr[0][j], b2 = hr[1][j], c2 = hr[2][j], d2 = hr[3][j];
            acc0 += w4.x * a.x + w4.y * a.y + w4.z * a.z + w4.w * a.w;
            acc1 += w4.x * b2.x + w4.y * b2.y + w4.z * b2.z + w4.w * b2.w;
            acc2 += w4.x * c2.x + w4.y * c2.y + w4.z * c2.z + w4.w * c2.w;
            acc3 += w4.x * d2.x + w4.y * d2.y + w4.z * d2.z + w4.w * d2.w;
        }
        float v[4] = {acc0, acc1, acc2, acc3};
        #pragma unroll
        for (int u = 0; u < 4; u++) {
            float a = fmaxf(v[u] + bpv, 0.f) * Wd[(size_t)sd[s[u]] * D_PW + kk];
            #pragma unroll
            for (int o = 16; o > 0; o >>= 1)
                a += __shfl_xor_sync(0xffffffffu, a, o);
            if (lane == 0) red[wrp * 4 + u] = a;
        }
        __syncthreads();
        if (tid < 8) {
            int gg = tid >> 2, u = tid & 3;
            int ss = 2 * (i0 + u) + gg;
            if (ss < nly) {
                float t = red[(gg * 4 + 0) * 4 + u] + red[(gg * 4 + 1) * 4 + u]
                        + red[(gg * 4 + 2) * 4 + u] + red[(gg * 4 + 3) * 4 + u];
                out[sb[ss]] = t + bd[sd[ss]];
            }
        }
        __syncthreads();
    }
}

// ---------------------------------------------------------------------------
// Launch
// ---------------------------------------------------------------------------
extern "C" void kernel_launch(void* const* d_in, const int* in_sizes, int n_in,
                              void* d_out, int out_size)
{
    const float* x   = (const float*)d_in[0];
    const float* W1  = (const float*)d_in[1];
    const float* b1  = (const float*)d_in[2];
    const float* W2  = (const float*)d_in[3];
    const float* b2  = (const float*)d_in[4];
    const float* Wp  = (const float*)d_in[5];
    const float* bp  = (const float*)d_in[6];
    const float* Wd  = (const float*)d_in[7];
    const float* bd  = (const float*)d_in[8];
    const int*   di  = (const int*)d_in[9];
    const int*   dpw = (const int*)d_in[10];
    float* out = (float*)d_out;

    void *p1, *p2, *p3, *p4;
    cudaGetSymbolAddress(&p1, g_h1);
    cudaGetSymbolAddress(&p2, g_h2);
    cudaGetSymbolAddress(&p3, g_w1r);
    cudaGetSymbolAddress(&p4, g_w2r);
    float* h1  = (float*)p1;
    float* h2  = (float*)p2;
    float* w1r = (float*)p3;
    float* w2r = (float*)p4;

    cudaFuncSetAttribute(gemm_bias_relu_kernel,
                         cudaFuncAttributeMaxDynamicSharedMemorySize, SMEM_BYTES);
    cudaFuncSetAttribute(head_kernel,
                         cudaFuncAttributeMaxDynamicSharedMemorySize, HEAD_SMEM_BYTES);

    // Index dtype + pathway buckets (graph-replay-safe)
    detect_idx_dtype_kernel<<<1, 256>>>(di);
    bucket_zero_kernel<<<1, 32>>>();
    bucket_fill_kernel<<<B_SZ / 256, 256>>>(di, dpw);

    // Pre-round weights to tf32 (rna): B fragments skip in-loop cvt
    {
        int n4 = (D_IN * D1) / 4;
        round_tf32_kernel<<<(n4 + 255) / 256, 256>>>(W1, w1r, n4);
        n4 = (D1 * D2) / 4;
        round_tf32_kernel<<<(n4 + 255) / 256, 256>>>(W2, w2r, n4);
    }

    // GEMM1: [8192,19200] @ [19200,512] -> h1
    gemm_bias_relu_kernel<<<dim3(B_SZ / BM, D1 / BN), NTHR, SMEM_BYTES>>>(
        x, w1r, b1, h1, B_SZ, D1, D_IN);
    // GEMM2: [8192,512] @ [512,256] -> h2
    gemm_bias_relu_kernel<<<dim3(B_SZ / BM, D2 / BN), NTHR, SMEM_BYTES>>>(
        h1, w2r, b2, h2, B_SZ, D2, D1);
    // Pathway-grouped head
    head_kernel<<<dim3((B_SZ + CHUNK - 1) / CHUNK, N_PW), 256, HEAD_SMEM_BYTES>>>(
        h2, Wp, bp, Wd, bd, di, out);
}

// round 13
// speedup vs baseline: 1.6061x; 1.0316x over previous
#include <cuda_runtime.h>
#include <cstdint>
#include <cstddef>

// ---------------------------------------------------------------------------
// Problem constants
// ---------------------------------------------------------------------------
#define B_SZ   8192
#define D_IN   19200
#define D1     512
#define D2     256
#define D_PW   128
#define N_PW   25
#define N_DRUG 1448

// ---------------------------------------------------------------------------
// GEMM tiling: 128x256 CTA tile, 16 warps of 32x64, BK=64, 2-stage cp.async
// (R5/R12-proven double-barrier loop; BK64 halves per-K sync overhead)
// ---------------------------------------------------------------------------
#define BM 128
#define BN 256
#define BK 64
#define STAGES 2
#define NTHR 512
#define ASTR 68    // padded A smem stride (floats): (68g+tg)%32 = 4g+tg unique
#define BSTR 264   // padded B smem stride (floats): (264tg+g)%32 = 8tg+g unique
#define SMEM_FLOATS (STAGES * (BM * ASTR + BK * BSTR))
#define SMEM_BYTES  (SMEM_FLOATS * 4)   // 204,800 B

// Head kernel
#define CHUNK 64
#define WSTR 260
#define HEAD_SMEM_BYTES ((128 * WSTR + CHUNK * 256 + 32) * 4 + CHUNK * 8 + 64)

// Scratch (allocation-free rule: __device__ globals)
__device__ float g_h1[B_SZ * D1];       // relu(x@W1+b1)
__device__ float g_h2[B_SZ * D2];       // relu(h1@W2+b2)
__device__ float g_w1r[D_IN * D1];      // W1 pre-rounded to tf32 (rna)
__device__ float g_w2r[D1 * D2];        // W2 pre-rounded to tf32 (rna)
__device__ int   g_idx64;               // 1 if drug_indices buffer is int64
__device__ int   g_cnt[N_PW];           // per-pathway sample counts
__device__ int   g_bucket[N_PW][B_SZ];  // per-pathway sample lists

// ---------------------------------------------------------------------------
// PTX helpers
// ---------------------------------------------------------------------------
__device__ __forceinline__ uint32_t f2tf32(float x) {
    uint32_t r;
    asm("cvt.rna.tf32.f32 %0, %1;" : "=r"(r) : "f"(x));
    return r;
}

__device__ __forceinline__ void cp16(float* s, const float* g) {
    uint32_t sa = (uint32_t)__cvta_generic_to_shared(s);
    asm volatile("cp.async.cg.shared.global [%0], [%1], 16;" :: "r"(sa), "l"(g));
}
__device__ __forceinline__ void cp_commit() {
    asm volatile("cp.async.commit_group;" ::: "memory");
}
__device__ __forceinline__ void cp_wait0() {
    asm volatile("cp.async.wait_group 0;" ::: "memory");
}

__device__ __forceinline__ void mma8(float* c, const uint32_t* a, const uint32_t* b) {
    asm volatile(
        "mma.sync.aligned.m16n8k8.row.col.f32.tf32.tf32.f32 "
        "{%0,%1,%2,%3}, {%4,%5,%6,%7}, {%8,%9}, {%0,%1,%2,%3};"
        : "+f"(c[0]), "+f"(c[1]), "+f"(c[2]), "+f"(c[3])
        : "r"(a[0]), "r"(a[1]), "r"(a[2]), "r"(a[3]),
          "r"(b[0]), "r"(b[1]));
}

// ---------------------------------------------------------------------------
// drug_indices dtype detection + pathway-count zeroing (merged so gemm1 can
// be launch #4 for ncu capture). int64 high words are all zero; int32 not.
// ---------------------------------------------------------------------------
__global__ void detect_zero_kernel(const int* __restrict__ di32) {
    __shared__ int s;
    if (threadIdx.x == 0) s = 0;
    if (threadIdx.x < N_PW) g_cnt[threadIdx.x] = 0;
    __syncthreads();
    int acc = 0;
    for (int i = threadIdx.x; i < B_SZ / 2; i += blockDim.x)
        acc |= di32[2 * i + 1];
    if (acc) atomicOr(&s, 1);
    __syncthreads();
    if (threadIdx.x == 0) g_idx64 = (s == 0) ? 1 : 0;
}

// ---------------------------------------------------------------------------
// Pathway bucketing (graph-replay safe; each out[b] written exactly once)
// ---------------------------------------------------------------------------
__global__ void bucket_fill_kernel(const int* __restrict__ di32,
                                   const int* __restrict__ drug_pw) {
    int b = blockIdx.x * blockDim.x + threadIdx.x;
    if (b >= B_SZ) return;
    int d = g_idx64 ? di32[2 * b] : di32[b];
    d = min(max(d, 0), N_DRUG - 1);
    int p = drug_pw[d];
    p = min(max(p, 0), N_PW - 1);
    int pos = atomicAdd(&g_cnt[p], 1);
    g_bucket[p][pos] = b;
}

// ---------------------------------------------------------------------------
// Elementwise round-to-tf32 (rna) copy: B fragments then skip in-loop cvt
// (HW truncation of an already-rounded value is the identity).
// ---------------------------------------------------------------------------
__global__ void round_tf32_kernel(const float* __restrict__ src,
                                  float* __restrict__ dst, int n4) {
    int i = blockIdx.x * blockDim.x + threadIdx.x;
    if (i >= n4) return;
    float4 v = reinterpret_cast<const float4*>(src)[i];
    v.x = __uint_as_float(f2tf32(v.x));
    v.y = __uint_as_float(f2tf32(v.y));
    v.z = __uint_as_float(f2tf32(v.z));
    v.w = __uint_as_float(f2tf32(v.w));
    reinterpret_cast<float4*>(dst)[i] = v;
}

// ---------------------------------------------------------------------------
// Fused GEMM + bias + ReLU:  C[M,N] = relu(A[M,K] @ B[K,N] + bias[N])
// TF32 mma.sync m16n8k8, 16 warps of 32x64, BK=64 2-stage cp.async,
// double-barrier loop. Requires M%128==0, N%256==0, K%64==0.
// Accumulation order per output element is k-ascending (identical to BK=32).
// ---------------------------------------------------------------------------
__global__ void __launch_bounds__(NTHR, 1) gemm_bias_relu_kernel(
    const float* __restrict__ A, const float* __restrict__ Bm,
    const float* __restrict__ bias, float* __restrict__ C,
    int M, int N, int K)
{
    extern __shared__ float smem[];
    float* sA = smem;                        // [STAGES][BM][ASTR]
    float* sB = smem + STAGES * BM * ASTR;   // [STAGES][BK][BSTR]

    const int tid  = threadIdx.x;
    const int warp = tid >> 5;
    const int lane = tid & 31;
    const int m0 = blockIdx.x * BM;
    const int n0 = blockIdx.y * BN;
    const int wm = (warp >> 2) * 32;   // 4 M-warps of 32 rows
    const int wn = (warp & 3) * 64;    // 4 N-warps of 64 cols
    const int g  = lane >> 2;          // 0..7
    const int tg = lane & 3;           // 0..3
    const int KT = K / BK;

    float acc[2][8][4];
    #pragma unroll
    for (int i = 0; i < 2; i++)
        #pragma unroll
        for (int j = 0; j < 8; j++)
            #pragma unroll
            for (int k = 0; k < 4; k++) acc[i][j][k] = 0.f;

    // cp.async lane assignments (512 threads, BK=64)
    const int ar = tid >> 4;          // 0..31 (A row), 4 passes of 32 rows
    const int ac = (tid & 15) * 4;    // A col float4 (0..60)
    const int br = tid >> 6;          // 0..7  (B row), 8 passes of 8 rows
    const int bc = (tid & 63) * 4;    // B col float4 (0..252)

    auto load_tile = [&](int stage, int kt) {
        const float* Ag = A + (size_t)m0 * K + (size_t)kt * BK;
        float* sAs = sA + stage * BM * ASTR;
        #pragma unroll
        for (int i = 0; i < 4; i++) {
            int r = ar + i * 32;
            cp16(sAs + r * ASTR + ac, Ag + (size_t)r * K + ac);
        }
        const float* Bg = Bm + (size_t)(kt * BK) * N + n0;
        float* sBs = sB + stage * BK * BSTR;
        #pragma unroll
        for (int i = 0; i < 8; i++) {
            int r = br + i * 8;
            cp16(sBs + r * BSTR + bc, Bg + (size_t)r * N + bc);
        }
    };

    auto compute_tile = [&](int stage) {
        const float* sAs = sA + stage * BM * ASTR + wm * ASTR;
        const float* sBs = sB + stage * BK * BSTR + wn;
        #pragma unroll
        for (int kk = 0; kk < 8; kk++) {
            const int k = kk * 8;
            uint32_t aF[2][4];
            uint32_t bF[8][2];
            #pragma unroll
            for (int mt = 0; mt < 2; mt++) {
                const float* ap = sAs + (mt * 16) * ASTR + k;
                aF[mt][0] = f2tf32(ap[g * ASTR + tg]);
                aF[mt][1] = f2tf32(ap[(g + 8) * ASTR + tg]);
                aF[mt][2] = f2tf32(ap[g * ASTR + tg + 4]);
                aF[mt][3] = f2tf32(ap[(g + 8) * ASTR + tg + 4]);
            }
            #pragma unroll
            for (int nt = 0; nt < 8; nt++) {
                // B pre-rounded to tf32: raw fragment bits, no cvt
                const float* bp_ = sBs + (k + tg) * BSTR + nt * 8 + g;
                bF[nt][0] = __float_as_uint(bp_[0]);
                bF[nt][1] = __float_as_uint(bp_[4 * BSTR]);
            }
            #pragma unroll
            for (int mt = 0; mt < 2; mt++)
                #pragma unroll
                for (int nt = 0; nt < 8; nt++)
                    mma8(acc[mt][nt], aF[mt], bF[nt]);
        }
    };

    // Prologue: fill stage 0
    load_tile(0, 0);
    cp_commit();

    // Mainloop: wait all; sync; issue next load (DMA overlaps compute); compute
    for (int kt = 0; kt < KT; kt++) {
        cp_wait0();
        __syncthreads();
        if (kt + 1 < KT) load_tile((kt + 1) & 1, kt + 1);
        cp_commit();
        compute_tile(kt & 1);
        __syncthreads();
    }

    // Epilogue: bias + relu, float2 stores
    #pragma unroll
    for (int mt = 0; mt < 2; mt++) {
        #pragma unroll
        for (int nt = 0; nt < 8; nt++) {
            int row = m0 + wm + mt * 16 + g;
            int col = n0 + wn + nt * 8 + 2 * tg;
            float bv0 = bias[col];
            float bv1 = bias[col + 1];
            float2 v0, v1;
            v0.x = fmaxf(acc[mt][nt][0] + bv0, 0.f);
            v0.y = fmaxf(acc[mt][nt][1] + bv1, 0.f);
            v1.x = fmaxf(acc[mt][nt][2] + bv0, 0.f);
            v1.y = fmaxf(acc[mt][nt][3] + bv1, 0.f);
            *reinterpret_cast<float2*>(C + (size_t)row * N + col)       = v0;
            *reinterpret_cast<float2*>(C + (size_t)(row + 8) * N + col) = v1;
        }
    }
}

// ---------------------------------------------------------------------------
// Pathway-grouped head (unchanged; ~25us)
// ---------------------------------------------------------------------------
__global__ void __launch_bounds__(256) head_kernel(
    const float* __restrict__ h2, const float* __restrict__ Wp,
    const float* __restrict__ bp, const float* __restrict__ Wd,
    const float* __restrict__ bd, const int* __restrict__ di32,
    float* __restrict__ out)
{
    const int p = blockIdx.y;
    const int c = blockIdx.x;
    const int n = g_cnt[p];
    if (c * CHUNK >= n) return;
    const int nly = min(CHUNK, n - c * CHUNK);

    extern __shared__ float hsm_raw[];
    float* ws  = hsm_raw;                       // [128][WSTR]
    float* hsm = ws + 128 * WSTR;               // [CHUNK][256]
    float* red = hsm + CHUNK * 256;             // [8][4]
    int*   sb  = (int*)(red + 32);              // [CHUNK]
    int*   sd  = sb + CHUNK;                    // [CHUNK]

    const int tid = threadIdx.x;

    if (tid < CHUNK) {
        if (tid < nly) {
            int b = g_bucket[p][c * CHUNK + tid];
            int d = g_idx64 ? di32[2 * b] : di32[b];
            d = min(max(d, 0), N_DRUG - 1);
            sb[tid] = b;
            sd[tid] = d;
        } else {
            sb[tid] = 0;
            sd[tid] = 0;
        }
    }

    {
        const float4* Wp4 = reinterpret_cast<const float4*>(Wp + (size_t)p * D_PW * 256);
        for (int idx = tid; idx < 128 * 64; idx += 256) {
            int r = idx >> 6, cc = idx & 63;
            float4 v = Wp4[idx];
            *reinterpret_cast<float4*>(ws + r * WSTR + cc * 4) = v;
        }
    }
    __syncthreads();

    for (int idx = tid; idx < nly * 64; idx += 256) {
        int s = idx >> 6, cc = idx & 63;
        float4 v = reinterpret_cast<const float4*>(h2 + (size_t)sb[s] * 256)[cc];
        *reinterpret_cast<float4*>(hsm + s * 256 + cc * 4) = v;
    }
    __syncthreads();

    const int kk  = tid & 127;
    const int grp = tid >> 7;
    const int wrp = tid >> 5;
    const int lane = tid & 31;
    const float bpv = bp[p * D_PW + kk];
    const float4* wrow = reinterpret_cast<const float4*>(ws + kk * WSTR);

    for (int i0 = 0; i0 < 32; i0 += 4) {
        int s[4];
        const float4* hr[4];
        #pragma unroll
        for (int u = 0; u < 4; u++) {
            s[u] = 2 * (i0 + u) + grp;
            hr[u] = reinterpret_cast<const float4*>(hsm + s[u] * 256);
        }
        float acc0 = 0.f, acc1 = 0.f, acc2 = 0.f, acc3 = 0.f;
        #pragma unroll 8
        for (int j = 0; j < 64; j++) {
            float4 w4 = wrow[j];
            float4 a = hr[0][j], b2 = hr[1][j], c2 = hr[2][j], d2 = hr[3][j];
            acc0 += w4.x * a.x + w4.y * a.y + w4.z * a.z + w4.w * a.w;
            acc1 += w4.x * b2.x + w4.y * b2.y + w4.z * b2.z + w4.w * b2.w;
            acc2 += w4.x * c2.x + w4.y * c2.y + w4.z * c2.z + w4.w * c2.w;
            acc3 += w4.x * d2.x + w4.y * d2.y + w4.z * d2.z + w4.w * d2.w;
        }
        float v[4] = {acc0, acc1, acc2, acc3};
        #pragma unroll
        for (int u = 0; u < 4; u++) {
            float a = fmaxf(v[u] + bpv, 0.f) * Wd[(size_t)sd[s[u]] * D_PW + kk];
            #pragma unroll
            for (int o = 16; o > 0; o >>= 1)
                a += __shfl_xor_sync(0xffffffffu, a, o);
            if (lane == 0) red[wrp * 4 + u] = a;
        }
        __syncthreads();
        if (tid < 8) {
            int gg = tid >> 2, u = tid & 3;
            int ss = 2 * (i0 + u) + gg;
            if (ss < nly) {
                float t = red[(gg * 4 + 0) * 4 + u] + red[(gg * 4 + 1) * 4 + u]
                        + red[(gg * 4 + 2) * 4 + u] + red[(gg * 4 + 3) * 4 + u];
                out[sb[ss]] = t + bd[sd[ss]];
            }
        }
        __syncthreads();
    }
}

// ---------------------------------------------------------------------------
// Launch — ordered so gemm1 is launch #4 (the slot ncu captures)
// ---------------------------------------------------------------------------
extern "C" void kernel_launch(void* const* d_in, const int* in_sizes, int n_in,
                              void* d_out, int out_size)
{
    const float* x   = (const float*)d_in[0];
    const float* W1  = (const float*)d_in[1];
    const float* b1  = (const float*)d_in[2];
    const float* W2  = (const float*)d_in[3];
    const float* b2  = (const float*)d_in[4];
    const float* Wp  = (const float*)d_in[5];
    const float* bp  = (const float*)d_in[6];
    const float* Wd  = (const float*)d_in[7];
    const float* bd  = (const float*)d_in[8];
    const int*   di  = (const int*)d_in[9];
    const int*   dpw = (const int*)d_in[10];
    float* out = (float*)d_out;

    void *p1, *p2, *p3, *p4;
    cudaGetSymbolAddress(&p1, g_h1);
    cudaGetSymbolAddress(&p2, g_h2);
    cudaGetSymbolAddress(&p3, g_w1r);
    cudaGetSymbolAddress(&p4, g_w2r);
    float* h1  = (float*)p1;
    float* h2  = (float*)p2;
    float* w1r = (float*)p3;
    float* w2r = (float*)p4;

    cudaFuncSetAttribute(gemm_bias_relu_kernel,
                         cudaFuncAttributeMaxDynamicSharedMemorySize, SMEM_BYTES);
    cudaFuncSetAttribute(head_kernel,
                         cudaFuncAttributeMaxDynamicSharedMemorySize, HEAD_SMEM_BYTES);

    // #1, #2: pre-round weights to tf32 (rna)
    {
        int n4 = (D_IN * D1) / 4;
        round_tf32_kernel<<<(n4 + 255) / 256, 256>>>(W1, w1r, n4);
        n4 = (D1 * D2) / 4;
        round_tf32_kernel<<<(n4 + 255) / 256, 256>>>(W2, w2r, n4);
    }
    // #3: index dtype + zero pathway counts
    detect_zero_kernel<<<1, 256>>>(di);
    // #4 (ncu capture slot): GEMM1 [8192,19200] @ [19200,512] -> h1
    gemm_bias_relu_kernel<<<dim3(B_SZ / BM, D1 / BN), NTHR, SMEM_BYTES>>>(
        x, w1r, b1, h1, B_SZ, D1, D_IN);
    // #5: pathway buckets (needs detect; head needs this)
    bucket_fill_kernel<<<B_SZ / 256, 256>>>(di, dpw);
    // #6: GEMM2 [8192,512] @ [512,256] -> h2
    gemm_bias_relu_kernel<<<dim3(B_SZ / BM, D2 / BN), NTHR, SMEM_BYTES>>>(
        h1, w2r, b2, h2, B_SZ, D2, D1);
    // #7: pathway-grouped head
    head_kernel<<<dim3((B_SZ + CHUNK - 1) / CHUNK, N_PW), 256, HEAD_SMEM_BYTES>>>(
        h2, Wp, bp, Wd, bd, di, out);
}

// round 14
// speedup vs baseline: 2.3516x; 1.4642x over previous
#include <cuda_runtime.h>
#include <cuda_fp16.h>
#include <cstdint>
#include <cstddef>

// ---------------------------------------------------------------------------
// Problem constants
// ---------------------------------------------------------------------------
#define B_SZ   8192
#define D_IN   19200
#define D1     512
#define D2     256
#define D_PW   128
#define N_PW   25
#define N_DRUG 1448

// ---------------------------------------------------------------------------
// GEMM tiling: 128x256 CTA tile, 16 warps of 32x64, BK=64 (fp16 m16n8k16),
// 3-stage cp.async, R5-proven double-barrier loop.
// All smem in uint32 units: A tile [BM][BK/2] pairs, B tile [BK/2][BN].
// ---------------------------------------------------------------------------
#define BM 128
#define BN 256
#define BK 64
#define KP (BK / 2)          // 32 k-pairs per tile
#define STAGES 3
#define NTHR 512
#define ASTR2 36             // A pair-stride: (36g+tg)%32 = 4g+tg unique
#define BSTR2 264            // B pair-stride: (264tg+g)%32 = 8tg+g unique
#define SMEM_U32  (STAGES * (BM * ASTR2 + KP * BSTR2))
#define SMEM_BYTES (SMEM_U32 * 4)      // 156,672 B

// Head kernel
#define CHUNK 64
#define WSTR 260
#define HEAD_SMEM_BYTES ((128 * WSTR + CHUNK * 256 + 32) * 4 + CHUNK * 8 + 64)

// Scratch (allocation-free rule: __device__ globals)
__device__ uint32_t g_xh[B_SZ * D_IN / 2];   // x as packed fp16 k-pairs
__device__ uint32_t g_w1h[D_IN / 2 * D1];    // W1 packed fp16 k-pairs [K/2][N]
__device__ uint32_t g_w2h[D1 / 2 * D2];      // W2 packed fp16 k-pairs
__device__ uint32_t g_h1h[B_SZ * D1 / 2];    // h1 packed fp16 k-pairs
__device__ float    g_h2[B_SZ * D2];         // h2 fp32 (head input)
__device__ int      g_idx64;
__device__ int      g_cnt[N_PW];
__device__ int      g_bucket[N_PW][B_SZ];

// ---------------------------------------------------------------------------
// PTX helpers
// ---------------------------------------------------------------------------
__device__ __forceinline__ uint32_t packh2(float a, float b) {
    __half2 h = __floats2half2_rn(a, b);
    return *reinterpret_cast<uint32_t*>(&h);
}

__device__ __forceinline__ void cp16(void* s, const void* g) {
    uint32_t sa = (uint32_t)__cvta_generic_to_shared(s);
    asm volatile("cp.async.cg.shared.global [%0], [%1], 16;" :: "r"(sa), "l"(g));
}
__device__ __forceinline__ void cp_commit() {
    asm volatile("cp.async.commit_group;" ::: "memory");
}
__device__ __forceinline__ void cp_wait1() {
    asm volatile("cp.async.wait_group 1;" ::: "memory");
}

// fp16 MMA, fp32 accumulate: D(16x8) += A(16x16) * B(16x8)
__device__ __forceinline__ void mma16(float* c, const uint32_t* a, const uint32_t* b) {
    asm volatile(
        "mma.sync.aligned.m16n8k16.row.col.f32.f16.f16.f32 "
        "{%0,%1,%2,%3}, {%4,%5,%6,%7}, {%8,%9}, {%0,%1,%2,%3};"
        : "+f"(c[0]), "+f"(c[1]), "+f"(c[2]), "+f"(c[3])
        : "r"(a[0]), "r"(a[1]), "r"(a[2]), "r"(a[3]),
          "r"(b[0]), "r"(b[1]));
}

// ---------------------------------------------------------------------------
// x -> packed fp16 pairs. Thread i: read float4 (2 pairs), write uint2.
// ---------------------------------------------------------------------------
__global__ void conv_x_kernel(const float* __restrict__ x, uint32_t* __restrict__ xh) {
    long long i = (long long)blockIdx.x * blockDim.x + threadIdx.x;
    const long long n = (long long)B_SZ * D_IN / 4;
    if (i >= n) return;
    float4 v = reinterpret_cast<const float4*>(x)[i];
    uint2 o;
    o.x = packh2(v.x, v.y);
    o.y = packh2(v.z, v.w);
    reinterpret_cast<uint2*>(xh)[i] = o;
}

// ---------------------------------------------------------------------------
// W1 + W2 -> packed fp16 k-pair layout: wh[k2*N + n] = pack(W[2k2][n], W[2k2+1][n])
// ---------------------------------------------------------------------------
#define W1_PAIRS (D_IN / 2 * D1)
#define W2_PAIRS (D1 / 2 * D2)
__global__ void conv_w_kernel(const float* __restrict__ W1f,
                              const float* __restrict__ W2f,
                              uint32_t* __restrict__ w1h,
                              uint32_t* __restrict__ w2h) {
    int i = blockIdx.x * blockDim.x + threadIdx.x;
    if (i < W1_PAIRS) {
        int k2 = i / D1, n = i % D1;
        w1h[i] = packh2(W1f[(size_t)(2 * k2) * D1 + n],
                        W1f[(size_t)(2 * k2 + 1) * D1 + n]);
    } else if (i < W1_PAIRS + W2_PAIRS) {
        int j = i - W1_PAIRS;
        int k2 = j / D2, n = j % D2;
        w2h[j] = packh2(W2f[(size_t)(2 * k2) * D2 + n],
                        W2f[(size_t)(2 * k2 + 1) * D2 + n]);
    }
}

// ---------------------------------------------------------------------------
// drug_indices dtype detection + pathway-count zeroing (merged)
// ---------------------------------------------------------------------------
__global__ void detect_zero_kernel(const int* __restrict__ di32) {
    __shared__ int s;
    if (threadIdx.x == 0) s = 0;
    if (threadIdx.x < N_PW) g_cnt[threadIdx.x] = 0;
    __syncthreads();
    int acc = 0;
    for (int i = threadIdx.x; i < B_SZ / 2; i += blockDim.x)
        acc |= di32[2 * i + 1];
    if (acc) atomicOr(&s, 1);
    __syncthreads();
    if (threadIdx.x == 0) g_idx64 = (s == 0) ? 1 : 0;
}

__global__ void bucket_fill_kernel(const int* __restrict__ di32,
                                   const int* __restrict__ drug_pw) {
    int b = blockIdx.x * blockDim.x + threadIdx.x;
    if (b >= B_SZ) return;
    int d = g_idx64 ? di32[2 * b] : di32[b];
    d = min(max(d, 0), N_DRUG - 1);
    int p = drug_pw[d];
    p = min(max(p, 0), N_PW - 1);
    int pos = atomicAdd(&g_cnt[p], 1);
    g_bucket[p][pos] = b;
}

// ---------------------------------------------------------------------------
// fp16 GEMM + bias + ReLU.  C[M,N] = relu(A @ B + bias)
// A: packed fp16 pairs [M][K/2] (u32); B: packed pairs [K/2][N] (u32).
// out_half: write C as packed fp16 pairs (u32 [M][N/2]); else fp32.
// 16 warps of 32x64; m16n8k16; 3-stage cp.async double-barrier loop.
// Requires M%128==0, N%256==0, K%64==0.
// ---------------------------------------------------------------------------
__global__ void __launch_bounds__(NTHR, 1) gemm_bias_relu_kernel(
    const uint32_t* __restrict__ A, const uint32_t* __restrict__ Bm,
    const float* __restrict__ bias, float* __restrict__ Cf,
    uint32_t* __restrict__ Ch, int M, int N, int K, int out_half)
{
    extern __shared__ uint32_t smem[];
    uint32_t* sA = smem;                         // [STAGES][BM][ASTR2]
    uint32_t* sB = smem + STAGES * BM * ASTR2;   // [STAGES][KP][BSTR2]

    const int tid  = threadIdx.x;
    const int warp = tid >> 5;
    const int lane = tid & 31;
    const int m0 = blockIdx.x * BM;
    const int n0 = blockIdx.y * BN;
    const int wm = (warp >> 2) * 32;   // 4 M-warps of 32 rows
    const int wn = (warp & 3) * 64;    // 4 N-warps of 64 cols
    const int g  = lane >> 2;          // 0..7
    const int tg = lane & 3;           // 0..3
    const int K2 = K / 2;
    const int KT = K / BK;

    float acc[2][8][4];
    #pragma unroll
    for (int i = 0; i < 2; i++)
        #pragma unroll
        for (int j = 0; j < 8; j++)
            #pragma unroll
            for (int k = 0; k < 4; k++) acc[i][j][k] = 0.f;

    // cp.async lane assignments (512 threads)
    const int ar = tid >> 3;          // 0..63 (A row), 2 passes of 64 rows
    const int ac = (tid & 7) * 4;     // A pair-col (u32 idx), 16B chunks
    const int br = tid >> 6;          // 0..7 (B pair-row), 4 passes of 8 rows
    const int bc = (tid & 63) * 4;    // B col (u32 idx)

    auto load_tile = [&](int stage, int kt) {
        const uint32_t* Ag = A + (size_t)m0 * K2 + (size_t)kt * KP;
        uint32_t* sAs = sA + stage * BM * ASTR2;
        #pragma unroll
        for (int i = 0; i < 2; i++) {
            int r = ar + i * 64;
            cp16(sAs + r * ASTR2 + ac, Ag + (size_t)r * K2 + ac);
        }
        const uint32_t* Bg = Bm + (size_t)(kt * KP) * N + n0;
        uint32_t* sBs = sB + stage * KP * BSTR2;
        #pragma unroll
        for (int i = 0; i < 4; i++) {
            int r = br + i * 8;
            cp16(sBs + r * BSTR2 + bc, Bg + (size_t)r * N + bc);
        }
    };

    auto compute_tile = [&](int stage) {
        const uint32_t* sAs = sA + stage * BM * ASTR2 + wm * ASTR2;
        const uint32_t* sBs = sB + stage * KP * BSTR2 + wn;
        #pragma unroll
        for (int kk = 0; kk < 4; kk++) {           // 4 k16 chunks per BK64
            const int kp = kk * 8;                 // pair offset
            uint32_t aF[2][4];
            uint32_t bF[8][2];
            #pragma unroll
            for (int mt = 0; mt < 2; mt++) {
                const uint32_t* ap = sAs + (mt * 16) * ASTR2 + kp;
                aF[mt][0] = ap[g * ASTR2 + tg];
                aF[mt][1] = ap[(g + 8) * ASTR2 + tg];
                aF[mt][2] = ap[g * ASTR2 + tg + 4];
                aF[mt][3] = ap[(g + 8) * ASTR2 + tg + 4];
            }
            #pragma unroll
            for (int nt = 0; nt < 8; nt++) {
                const uint32_t* bp_ = sBs + (kp + tg) * BSTR2 + nt * 8 + g;
                bF[nt][0] = bp_[0];
                bF[nt][1] = bp_[4 * BSTR2];
            }
            #pragma unroll
            for (int mt = 0; mt < 2; mt++)
                #pragma unroll
                for (int nt = 0; nt < 8; nt++)
                    mma16(acc[mt][nt], aF[mt], bF[nt]);
        }
    };

    // Prologue: fill STAGES-1 stages
    load_tile(0, 0);
    cp_commit();
    if (KT > 1) load_tile(1, 1);
    cp_commit();

    // Mainloop (proven skeleton): wait; sync; load next; commit; compute; sync
    for (int kt = 0; kt < KT; kt++) {
        cp_wait1();
        __syncthreads();
        int nk = kt + STAGES - 1;
        if (nk < KT) load_tile(nk % STAGES, nk);
        cp_commit();
        compute_tile(kt % STAGES);
        __syncthreads();
    }

    // Epilogue: bias + relu; pack to fp16 pairs (GEMM1) or fp32 (GEMM2)
    #pragma unroll
    for (int mt = 0; mt < 2; mt++) {
        #pragma unroll
        for (int nt = 0; nt < 8; nt++) {
            int row = m0 + wm + mt * 16 + g;
            int col = n0 + wn + nt * 8 + 2 * tg;     // even
            float bv0 = bias[col];
            float bv1 = bias[col + 1];
            float v00 = fmaxf(acc[mt][nt][0] + bv0, 0.f);
            float v01 = fmaxf(acc[mt][nt][1] + bv1, 0.f);
            float v10 = fmaxf(acc[mt][nt][2] + bv0, 0.f);
            float v11 = fmaxf(acc[mt][nt][3] + bv1, 0.f);
            if (out_half) {
                Ch[(size_t)row * (N / 2) + col / 2]       = packh2(v00, v01);
                Ch[(size_t)(row + 8) * (N / 2) + col / 2] = packh2(v10, v11);
            } else {
                float2 a = {v00, v01}, b = {v10, v11};
                *reinterpret_cast<float2*>(Cf + (size_t)row * N + col)       = a;
                *reinterpret_cast<float2*>(Cf + (size_t)(row + 8) * N + col) = b;
            }
        }
    }
}

// ---------------------------------------------------------------------------
// Pathway-grouped head (unchanged; h2 fp32)
// ---------------------------------------------------------------------------
__global__ void __launch_bounds__(256) head_kernel(
    const float* __restrict__ h2, const float* __restrict__ Wp,
    const float* __restrict__ bp, const float* __restrict__ Wd,
    const float* __restrict__ bd, const int* __restrict__ di32,
    float* __restrict__ out)
{
    const int p = blockIdx.y;
    const int c = blockIdx.x;
    const int n = g_cnt[p];
    if (c * CHUNK >= n) return;
    const int nly = min(CHUNK, n - c * CHUNK);

    extern __shared__ float hsm_raw[];
    float* ws  = hsm_raw;                       // [128][WSTR]
    float* hsm = ws + 128 * WSTR;               // [CHUNK][256]
    float* red = hsm + CHUNK * 256;             // [8][4]
    int*   sb  = (int*)(red + 32);              // [CHUNK]
    int*   sd  = sb + CHUNK;                    // [CHUNK]

    const int tid = threadIdx.x;

    if (tid < CHUNK) {
        if (tid < nly) {
            int b = g_bucket[p][c * CHUNK + tid];
            int d = g_idx64 ? di32[2 * b] : di32[b];
            d = min(max(d, 0), N_DRUG - 1);
            sb[tid] = b;
            sd[tid] = d;
        } else {
            sb[tid] = 0;
            sd[tid] = 0;
        }
    }

    {
        const float4* Wp4 = reinterpret_cast<const float4*>(Wp + (size_t)p * D_PW * 256);
        for (int idx = tid; idx < 128 * 64; idx += 256) {
            int r = idx >> 6, cc = idx & 63;
            float4 v = Wp4[idx];
            *reinterpret_cast<float4*>(ws + r * WSTR + cc * 4) = v;
        }
    }
    __syncthreads();

    for (int idx = tid; idx < nly * 64; idx += 256) {
        int s = idx >> 6, cc = idx & 63;
        float4 v = reinterpret_cast<const float4*>(h2 + (size_t)sb[s] * 256)[cc];
        *reinterpret_cast<float4*>(hsm + s * 256 + cc * 4) = v;
    }
    __syncthreads();

    const int kk  = tid & 127;
    const int grp = tid >> 7;
    const int wrp = tid >> 5;
    const int lane = tid & 31;
    const float bpv = bp[p * D_PW + kk];
    const float4* wrow = reinterpret_cast<const float4*>(ws + kk * WSTR);

    for (int i0 = 0; i0 < 32; i0 += 4) {
        int s[4];
        const float4* hr[4];
        #pragma unroll
        for (int u = 0; u < 4; u++) {
            s[u] = 2 * (i0 + u) + grp;
            hr[u] = reinterpret_cast<const float4*>(hsm + s[u] * 256);
        }
        float acc0 = 0.f, acc1 = 0.f, acc2 = 0.f, acc3 = 0.f;
        #pragma unroll 8
        for (int j = 0; j < 64; j++) {
            float4 w4 = wrow[j];
            float4 a = hr[0][j], b2 = hr[1][j], c2 = hr[2][j], d2 = hr[3][j];
            acc0 += w4.x * a.x + w4.y * a.y + w4.z * a.z + w4.w * a.w;
            acc1 += w4.x * b2.x + w4.y * b2.y + w4.z * b2.z + w4.w * b2.w;
            acc2 += w4.x * c2.x + w4.y * c2.y + w4.z * c2.z + w4.w * c2.w;
            acc3 += w4.x * d2.x + w4.y * d2.y + w4.z * d2.z + w4.w * d2.w;
        }
        float v[4] = {acc0, acc1, acc2, acc3};
        #pragma unroll
        for (int u = 0; u < 4; u++) {
            float a = fmaxf(v[u] + bpv, 0.f) * Wd[(size_t)sd[s[u]] * D_PW + kk];
            #pragma unroll
            for (int o = 16; o > 0; o >>= 1)
                a += __shfl_xor_sync(0xffffffffu, a, o);
            if (lane == 0) red[wrp * 4 + u] = a;
        }
        __syncthreads();
        if (tid < 8) {
            int gg = tid >> 2, u = tid & 3;
            int ss = 2 * (i0 + u) + gg;
            if (ss < nly) {
                float t = red[(gg * 4 + 0) * 4 + u] + red[(gg * 4 + 1) * 4 + u]
                        + red[(gg * 4 + 2) * 4 + u] + red[(gg * 4 + 3) * 4 + u];
                out[sb[ss]] = t + bd[sd[ss]];
            }
        }
        __syncthreads();
    }
}

// ---------------------------------------------------------------------------
// Launch — gemm1 kept at slot #4 (the launch ncu captures)
// ---------------------------------------------------------------------------
extern "C" void kernel_launch(void* const* d_in, const int* in_sizes, int n_in,
                              void* d_out, int out_size)
{
    const float* x   = (const float*)d_in[0];
    const float* W1  = (const float*)d_in[1];
    const float* b1  = (const float*)d_in[2];
    const float* W2  = (const float*)d_in[3];
    const float* b2  = (const float*)d_in[4];
    const float* Wp  = (const float*)d_in[5];
    const float* bp  = (const float*)d_in[6];
    const float* Wd  = (const float*)d_in[7];
    const float* bd  = (const float*)d_in[8];
    const int*   di  = (const int*)d_in[9];
    const int*   dpw = (const int*)d_in[10];
    float* out = (float*)d_out;

    void *pxh, *pw1, *pw2, *ph1, *ph2;
    cudaGetSymbolAddress(&pxh, g_xh);
    cudaGetSymbolAddress(&pw1, g_w1h);
    cudaGetSymbolAddress(&pw2, g_w2h);
    cudaGetSymbolAddress(&ph1, g_h1h);
    cudaGetSymbolAddress(&ph2, g_h2);
    uint32_t* xh  = (uint32_t*)pxh;
    uint32_t* w1h = (uint32_t*)pw1;
    uint32_t* w2h = (uint32_t*)pw2;
    uint32_t* h1h = (uint32_t*)ph1;
    float*    h2  = (float*)ph2;

    cudaFuncSetAttribute(gemm_bias_relu_kernel,
                         cudaFuncAttributeMaxDynamicSharedMemorySize, SMEM_BYTES);
    cudaFuncSetAttribute(head_kernel,
                         cudaFuncAttributeMaxDynamicSharedMemorySize, HEAD_SMEM_BYTES);

    // #1: x -> packed fp16 pairs
    {
        long long n = (long long)B_SZ * D_IN / 4;
        conv_x_kernel<<<(int)((n + 255) / 256), 256>>>(x, xh);
    }
    // #2: W1 + W2 -> packed fp16 pairs
    {
        int n = W1_PAIRS + W2_PAIRS;
        conv_w_kernel<<<(n + 255) / 256, 256>>>(W1, W2, w1h, w2h);
    }
    // #3: index dtype + zero pathway counts
    detect_zero_kernel<<<1, 256>>>(di);
    // #4 (ncu capture slot): GEMM1 -> h1 (packed fp16)
    gemm_bias_relu_kernel<<<dim3(B_SZ / BM, D1 / BN), NTHR, SMEM_BYTES>>>(
        xh, w1h, b1, nullptr, h1h, B_SZ, D1, D_IN, 1);
    // #5: pathway buckets
    bucket_fill_kernel<<<B_SZ / 256, 256>>>(di, dpw);
    // #6: GEMM2 -> h2 (fp32)
    gemm_bias_relu_kernel<<<dim3(B_SZ / BM, D2 / BN), NTHR, SMEM_BYTES>>>(
        h1h, w2h, b2, h2, nullptr, B_SZ, D2, D1, 0);
    // #7: pathway-grouped head
    head_kernel<<<dim3((B_SZ + CHUNK - 1) / CHUNK, N_PW), 256, HEAD_SMEM_BYTES>>>(
        h2, Wp, bp, Wd, bd, di, out);
}

// round 15
// speedup vs baseline: 2.4472x; 1.0407x over previous
#include <cuda_runtime.h>
#include <cuda_fp16.h>
#include <cstdint>
#include <cstddef>

// ---------------------------------------------------------------------------
// Problem constants
// ---------------------------------------------------------------------------
#define B_SZ   8192
#define D_IN   19200
#define D1     512
#define D2     256
#define D_PW   128
#define N_PW   25
#define N_DRUG 1448

// ---------------------------------------------------------------------------
// GEMM tiling: 128x256 CTA, 16 warps of 32x64, BK=64, fp16 m16n8k16,
// ldmatrix fragment loads, 3-stage cp.async double-barrier loop.
// A smem: [BM][ASTR2] u32 (fp16 pairs along k). B smem: [BK][BROW2] u32
// rows = k, fp16 halves along n.
// ---------------------------------------------------------------------------
#define BM 128
#define BN 256
#define BK 64
#define KP 32                 // A: 32 u32 k-pairs per tile row
#define STAGES 3
#define NTHR 512
#define ASTR2 36              // A row stride (u32): 36 % 32 = 4 -> conflict-free
#define BROW2 132             // B row stride (u32): 264 halves; 132 % 32 = 4
#define A_STG_U32 (BM * ASTR2)          // 4608
#define B_STG_U32 (BK * BROW2)          // 8448
#define A_TOT_U32 (STAGES * A_STG_U32)  // 13824
#define SMEM_U32  (A_TOT_U32 + STAGES * B_STG_U32)
#define SMEM_BYTES (SMEM_U32 * 4)       // 156,672 B

// Head kernel
#define CHUNK 64
#define WSTR 260
#define HEAD_SMEM_BYTES ((128 * WSTR + CHUNK * 256 + 32) * 4 + CHUNK * 8 + 64)

// Scratch (allocation-free rule: __device__ globals)
__device__ __half g_xh[B_SZ * D_IN];     // x as fp16 [M][K]
__device__ __half g_w1h[D_IN * D1];      // W1 fp16 [K][N] (natural layout)
__device__ __half g_w2h[D1 * D2];        // W2 fp16 [K][N]
__device__ __half g_h1h[B_SZ * D1];      // h1 fp16 [M][K] for gemm2
__device__ float  g_h2[B_SZ * D2];       // h2 fp32 (head input)
__device__ int    g_idx64;
__device__ int    g_cnt[N_PW];
__device__ int    g_bucket[N_PW][B_SZ];

// ---------------------------------------------------------------------------
// PTX helpers
// ---------------------------------------------------------------------------
__device__ __forceinline__ uint32_t packh2(float a, float b) {
    __half2 h = __floats2half2_rn(a, b);
    return *reinterpret_cast<uint32_t*>(&h);
}

__device__ __forceinline__ void cp16(void* s, const void* g) {
    uint32_t sa = (uint32_t)__cvta_generic_to_shared(s);
    asm volatile("cp.async.cg.shared.global [%0], [%1], 16;" :: "r"(sa), "l"(g));
}
__device__ __forceinline__ void cp_commit() {
    asm volatile("cp.async.commit_group;" ::: "memory");
}
__device__ __forceinline__ void cp_wait1() {
    asm volatile("cp.async.wait_group 1;" ::: "memory");
}

__device__ __forceinline__ void ldsm4(uint32_t* r, uint32_t addr) {
    asm volatile("ldmatrix.sync.aligned.m8n8.x4.shared.b16 {%0,%1,%2,%3}, [%4];"
        : "=r"(r[0]), "=r"(r[1]), "=r"(r[2]), "=r"(r[3]) : "r"(addr));
}
__device__ __forceinline__ void ldsm4t(uint32_t* r, uint32_t addr) {
    asm volatile("ldmatrix.sync.aligned.m8n8.x4.trans.shared.b16 {%0,%1,%2,%3}, [%4];"
        : "=r"(r[0]), "=r"(r[1]), "=r"(r[2]), "=r"(r[3]) : "r"(addr));
}

__device__ __forceinline__ void mma16(float* c, const uint32_t* a, const uint32_t* b) {
    asm volatile(
        "mma.sync.aligned.m16n8k16.row.col.f32.f16.f16.f32 "
        "{%0,%1,%2,%3}, {%4,%5,%6,%7}, {%8,%9}, {%0,%1,%2,%3};"
        : "+f"(c[0]), "+f"(c[1]), "+f"(c[2]), "+f"(c[3])
        : "r"(a[0]), "r"(a[1]), "r"(a[2]), "r"(a[3]),
          "r"(b[0]), "r"(b[1]));
}

// ---------------------------------------------------------------------------
// x -> fp16 (natural [M][K] layout)
// ---------------------------------------------------------------------------
__global__ void conv_x_kernel(const float* __restrict__ x, __half* __restrict__ xh) {
    long long i = (long long)blockIdx.x * blockDim.x + threadIdx.x;
    const long long n = (long long)B_SZ * D_IN / 4;
    if (i >= n) return;
    float4 v = reinterpret_cast<const float4*>(x)[i];
    uint2 o;
    o.x = packh2(v.x, v.y);
    o.y = packh2(v.z, v.w);
    reinterpret_cast<uint2*>(xh)[i] = o;
}

// ---------------------------------------------------------------------------
// W1 + W2 -> fp16, elementwise (natural [K][N] layout)
// ---------------------------------------------------------------------------
#define W1_Q (D_IN * D1 / 4)
#define W2_Q (D1 * D2 / 4)
__global__ void conv_w_kernel(const float* __restrict__ W1f,
                              const float* __restrict__ W2f,
                              __half* __restrict__ w1h,
                              __half* __restrict__ w2h) {
    int i = blockIdx.x * blockDim.x + threadIdx.x;
    if (i < W1_Q) {
        float4 v = reinterpret_cast<const float4*>(W1f)[i];
        uint2 o;
        o.x = packh2(v.x, v.y);
        o.y = packh2(v.z, v.w);
        reinterpret_cast<uint2*>(w1h)[i] = o;
    } else if (i < W1_Q + W2_Q) {
        int j = i - W1_Q;
        float4 v = reinterpret_cast<const float4*>(W2f)[j];
        uint2 o;
        o.x = packh2(v.x, v.y);
        o.y = packh2(v.z, v.w);
        reinterpret_cast<uint2*>(w2h)[j] = o;
    }
}

// ---------------------------------------------------------------------------
// drug_indices dtype detection + pathway-count zeroing (merged)
// ---------------------------------------------------------------------------
__global__ void detect_zero_kernel(const int* __restrict__ di32) {
    __shared__ int s;
    if (threadIdx.x == 0) s = 0;
    if (threadIdx.x < N_PW) g_cnt[threadIdx.x] = 0;
    __syncthreads();
    int acc = 0;
    for (int i = threadIdx.x; i < B_SZ / 2; i += blockDim.x)
        acc |= di32[2 * i + 1];
    if (acc) atomicOr(&s, 1);
    __syncthreads();
    if (threadIdx.x == 0) g_idx64 = (s == 0) ? 1 : 0;
}

__global__ void bucket_fill_kernel(const int* __restrict__ di32,
                                   const int* __restrict__ drug_pw) {
    int b = blockIdx.x * blockDim.x + threadIdx.x;
    if (b >= B_SZ) return;
    int d = g_idx64 ? di32[2 * b] : di32[b];
    d = min(max(d, 0), N_DRUG - 1);
    int p = drug_pw[d];
    p = min(max(p, 0), N_PW - 1);
    int pos = atomicAdd(&g_cnt[p], 1);
    g_bucket[p][pos] = b;
}

// ---------------------------------------------------------------------------
// fp16 GEMM + bias + ReLU.  C[M,N] = relu(A @ B + bias)
// A: fp16 [M][K]; B: fp16 [K][N]. ldmatrix fragments, m16n8k16.
// out_half: C as fp16 [M][N]; else fp32. M%128==0, N%256==0, K%64==0.
// ---------------------------------------------------------------------------
__global__ void __launch_bounds__(NTHR, 1) gemm_bias_relu_kernel(
    const uint32_t* __restrict__ A, const __half* __restrict__ Bh,
    const float* __restrict__ bias, float* __restrict__ Cf,
    uint32_t* __restrict__ Ch, int M, int N, int K, int out_half)
{
    extern __shared__ uint32_t smem[];
    uint32_t* sA = smem;                     // [STAGES][BM][ASTR2]
    uint32_t* sB = smem + A_TOT_U32;         // [STAGES][BK][BROW2]
    const uint32_t sbase = (uint32_t)__cvta_generic_to_shared(smem);

    const int tid  = threadIdx.x;
    const int warp = tid >> 5;
    const int lane = tid & 31;
    const int m0 = blockIdx.x * BM;
    const int n0 = blockIdx.y * BN;
    const int wm = (warp >> 2) * 32;   // 4 M-warps of 32 rows
    const int wn = (warp & 3) * 64;    // 4 N-warps of 64 cols
    const int g  = lane >> 2;          // 0..7
    const int tg = lane & 3;           // 0..3
    const int K2 = K / 2;
    const int KT = K / BK;

    // ldmatrix per-lane address components (matrix id m = lane>>3)
    const int mrow = (lane & 7) + ((lane >> 3) & 1) * 8;   // row within 16
    const int mcol = (lane >> 4) * 4;                      // u32 col: 0 or 4
    const uint32_t aoff0 = (uint32_t)(((wm + mrow) * ASTR2 + mcol) * 4);
    const uint32_t aoff1 = aoff0 + 16 * ASTR2 * 4;
    const uint32_t boff  = (uint32_t)((mrow * BROW2 + mcol) * 4 + wn * 2);

    float acc[2][8][4];
    #pragma unroll
    for (int i = 0; i < 2; i++)
        #pragma unroll
        for (int j = 0; j < 8; j++)
            #pragma unroll
            for (int k = 0; k < 4; k++) acc[i][j][k] = 0.f;

    // cp.async lane assignments (512 threads)
    const int ar = tid >> 3;          // 0..63 (A row), 2 passes of 64 rows
    const int ac = (tid & 7) * 4;     // A u32 col (16B chunks)
    const int br = tid >> 3;          // 0..63 (B k-row)
    const int bc = tid & 7;           // B 16B-chunk base (of 32 per row)

    auto load_tile = [&](int stage, int kt) {
        const uint32_t* Ag = A + (size_t)m0 * K2 + (size_t)kt * KP;
        uint32_t* sAs = sA + stage * A_STG_U32;
        #pragma unroll
        for (int i = 0; i < 2; i++) {
            int r = ar + i * 64;
            cp16(sAs + r * ASTR2 + ac, Ag + (size_t)r * K2 + ac);
        }
        const __half* Bg = Bh + (size_t)(kt * BK) * N + n0;
        uint32_t* sBs = sB + stage * B_STG_U32;
        #pragma unroll
        for (int i = 0; i < 4; i++) {
            int c = bc + i * 8;
            cp16(sBs + br * BROW2 + c * 4, Bg + (size_t)br * N + c * 8);
        }
    };

    auto compute_tile = [&](int stage) {
        const uint32_t abase = sbase + (stage * A_STG_U32) * 4;
        const uint32_t bbase = sbase + (A_TOT_U32 + stage * B_STG_U32) * 4;
        #pragma unroll
        for (int kk = 0; kk < 4; kk++) {     // 4 k16 chunks per BK64
            uint32_t aF[2][4];
            uint32_t bF[4][4];
            ldsm4(aF[0], abase + aoff0 + kk * 32);
            ldsm4(aF[1], abase + aoff1 + kk * 32);
            #pragma unroll
            for (int nn = 0; nn < 4; nn++)
                ldsm4t(bF[nn], bbase + boff + kk * (16 * BROW2 * 4) + nn * 32);
            #pragma unroll
            for (int mt = 0; mt < 2; mt++)
                #pragma unroll
                for (int nt = 0; nt < 8; nt++)
                    mma16(acc[mt][nt], aF[mt], &bF[nt >> 1][(nt & 1) * 2]);
        }
    };

    // Prologue: fill STAGES-1 stages
    load_tile(0, 0);
    cp_commit();
    if (KT > 1) load_tile(1, 1);
    cp_commit();

    // Mainloop (proven skeleton)
    for (int kt = 0; kt < KT; kt++) {
        cp_wait1();
        __syncthreads();
        int nk = kt + STAGES - 1;
        if (nk < KT) load_tile(nk % STAGES, nk);
        cp_commit();
        compute_tile(kt % STAGES);
        __syncthreads();
    }

    // Epilogue: bias + relu; fp16 pairs (GEMM1) or fp32 (GEMM2)
    #pragma unroll
    for (int mt = 0; mt < 2; mt++) {
        #pragma unroll
        for (int nt = 0; nt < 8; nt++) {
            int row = m0 + wm + mt * 16 + g;
            int col = n0 + wn + nt * 8 + 2 * tg;
            float bv0 = bias[col];
            float bv1 = bias[col + 1];
            float v00 = fmaxf(acc[mt][nt][0] + bv0, 0.f);
            float v01 = fmaxf(acc[mt][nt][1] + bv1, 0.f);
            float v10 = fmaxf(acc[mt][nt][2] + bv0, 0.f);
            float v11 = fmaxf(acc[mt][nt][3] + bv1, 0.f);
            if (out_half) {
                Ch[(size_t)row * (N / 2) + col / 2]       = packh2(v00, v01);
                Ch[(size_t)(row + 8) * (N / 2) + col / 2] = packh2(v10, v11);
            } else {
                float2 a = {v00, v01}, b = {v10, v11};
                *reinterpret_cast<float2*>(Cf + (size_t)row * N + col)       = a;
                *reinterpret_cast<float2*>(Cf + (size_t)(row + 8) * N + col) = b;
            }
        }
    }
}

// ---------------------------------------------------------------------------
// Pathway-grouped head (unchanged)
// ---------------------------------------------------------------------------
__global__ void __launch_bounds__(256) head_kernel(
    const float* __restrict__ h2, const float* __restrict__ Wp,
    const float* __restrict__ bp, const float* __restrict__ Wd,
    const float* __restrict__ bd, const int* __restrict__ di32,
    float* __restrict__ out)
{
    const int p = blockIdx.y;
    const int c = blockIdx.x;
    const int n = g_cnt[p];
    if (c * CHUNK >= n) return;
    const int nly = min(CHUNK, n - c * CHUNK);

    extern __shared__ float hsm_raw[];
    float* ws  = hsm_raw;
    float* hsm = ws + 128 * WSTR;
    float* red = hsm + CHUNK * 256;
    int*   sb  = (int*)(red + 32);
    int*   sd  = sb + CHUNK;

    const int tid = threadIdx.x;

    if (tid < CHUNK) {
        if (tid < nly) {
            int b = g_bucket[p][c * CHUNK + tid];
            int d = g_idx64 ? di32[2 * b] : di32[b];
            d = min(max(d, 0), N_DRUG - 1);
            sb[tid] = b;
            sd[tid] = d;
        } else {
            sb[tid] = 0;
            sd[tid] = 0;
        }
    }

    {
        const float4* Wp4 = reinterpret_cast<const float4*>(Wp + (size_t)p * D_PW * 256);
        for (int idx = tid; idx < 128 * 64; idx += 256) {
            int r = idx >> 6, cc = idx & 63;
            float4 v = Wp4[idx];
            *reinterpret_cast<float4*>(ws + r * WSTR + cc * 4) = v;
        }
    }
    __syncthreads();

    for (int idx = tid; idx < nly * 64; idx += 256) {
        int s = idx >> 6, cc = idx & 63;
        float4 v = reinterpret_cast<const float4*>(h2 + (size_t)sb[s] * 256)[cc];
        *reinterpret_cast<float4*>(hsm + s * 256 + cc * 4) = v;
    }
    __syncthreads();

    const int kk  = tid & 127;
    const int grp = tid >> 7;
    const int wrp = tid >> 5;
    const int lane = tid & 31;
    const float bpv = bp[p * D_PW + kk];
    const float4* wrow = reinterpret_cast<const float4*>(ws + kk * WSTR);

    for (int i0 = 0; i0 < 32; i0 += 4) {
        int s[4];
        const float4* hr[4];
        #pragma unroll
        for (int u = 0; u < 4; u++) {
            s[u] = 2 * (i0 + u) + grp;
            hr[u] = reinterpret_cast<const float4*>(hsm + s[u] * 256);
        }
        float acc0 = 0.f, acc1 = 0.f, acc2 = 0.f, acc3 = 0.f;
        #pragma unroll 8
        for (int j = 0; j < 64; j++) {
            float4 w4 = wrow[j];
            float4 a = hr[0][j], b2 = hr[1][j], c2 = hr[2][j], d2 = hr[3][j];
            acc0 += w4.x * a.x + w4.y * a.y + w4.z * a.z + w4.w * a.w;
            acc1 += w4.x * b2.x + w4.y * b2.y + w4.z * b2.z + w4.w * b2.w;
            acc2 += w4.x * c2.x + w4.y * c2.y + w4.z * c2.z + w4.w * c2.w;
            acc3 += w4.x * d2.x + w4.y * d2.y + w4.z * d2.z + w4.w * d2.w;
        }
        float v[4] = {acc0, acc1, acc2, acc3};
        #pragma unroll
        for (int u = 0; u < 4; u++) {
            float a = fmaxf(v[u] + bpv, 0.f) * Wd[(size_t)sd[s[u]] * D_PW + kk];
            #pragma unroll
            for (int o = 16; o > 0; o >>= 1)
                a += __shfl_xor_sync(0xffffffffu, a, o);
            if (lane == 0) red[wrp * 4 + u] = a;
        }
        __syncthreads();
        if (tid < 8) {
            int gg = tid >> 2, u = tid & 3;
            int ss = 2 * (i0 + u) + gg;
            if (ss < nly) {
                float t = red[(gg * 4 + 0) * 4 + u] + red[(gg * 4 + 1) * 4 + u]
                        + red[(gg * 4 + 2) * 4 + u] + red[(gg * 4 + 3) * 4 + u];
                out[sb[ss]] = t + bd[sd[ss]];
            }
        }
        __syncthreads();
    }
}

// ---------------------------------------------------------------------------
// Launch — gemm1 kept at slot #4 (the launch ncu captures)
// ---------------------------------------------------------------------------
extern "C" void kernel_launch(void* const* d_in, const int* in_sizes, int n_in,
                              void* d_out, int out_size)
{
    const float* x   = (const float*)d_in[0];
    const float* W1  = (const float*)d_in[1];
    const float* b1  = (const float*)d_in[2];
    const float* W2  = (const float*)d_in[3];
    const float* b2  = (const float*)d_in[4];
    const float* Wp  = (const float*)d_in[5];
    const float* bp  = (const float*)d_in[6];
    const float* Wd  = (const float*)d_in[7];
    const float* bd  = (const float*)d_in[8];
    const int*   di  = (const int*)d_in[9];
    const int*   dpw = (const int*)d_in[10];
    float* out = (float*)d_out;

    void *pxh, *pw1, *pw2, *ph1, *ph2;
    cudaGetSymbolAddress(&pxh, g_xh);
    cudaGetSymbolAddress(&pw1, g_w1h);
    cudaGetSymbolAddress(&pw2, g_w2h);
    cudaGetSymbolAddress(&ph1, g_h1h);
    cudaGetSymbolAddress(&ph2, g_h2);
    __half* xh  = (__half*)pxh;
    __half* w1h = (__half*)pw1;
    __half* w2h = (__half*)pw2;
    __half* h1h = (__half*)ph1;
    float*  h2  = (float*)ph2;

    cudaFuncSetAttribute(gemm_bias_relu_kernel,
                         cudaFuncAttributeMaxDynamicSharedMemorySize, SMEM_BYTES);
    cudaFuncSetAttribute(head_kernel,
                         cudaFuncAttributeMaxDynamicSharedMemorySize, HEAD_SMEM_BYTES);

    // #1: x -> fp16
    {
        long long n = (long long)B_SZ * D_IN / 4;
        conv_x_kernel<<<(int)((n + 255) / 256), 256>>>(x, xh);
    }
    // #2: W1 + W2 -> fp16 (elementwise)
    {
        int n = W1_Q + W2_Q;
        conv_w_kernel<<<(n + 255) / 256, 256>>>(W1, W2, w1h, w2h);
    }
    // #3: index dtype + zero pathway counts
    detect_zero_kernel<<<1, 256>>>(di);
    // #4 (ncu capture slot): GEMM1 -> h1 (fp16)
    gemm_bias_relu_kernel<<<dim3(B_SZ / BM, D1 / BN), NTHR, SMEM_BYTES>>>(
        (const uint32_t*)xh, w1h, b1, nullptr, (uint32_t*)h1h, B_SZ, D1, D_IN, 1);
    // #5: pathway buckets
    bucket_fill_kernel<<<B_SZ / 256, 256>>>(di, dpw);
    // #6: GEMM2 -> h2 (fp32)
    gemm_bias_relu_kernel<<<dim3(B_SZ / BM, D2 / BN), NTHR, SMEM_BYTES>>>(
        (const uint32_t*)h1h, w2h, b2, h2, nullptr, B_SZ, D2, D1, 0);
    // #7: pathway-grouped head
    head_kernel<<<dim3((B_SZ + CHUNK - 1) / CHUNK, N_PW), 256, HEAD_SMEM_BYTES>>>(
        h2, Wp, bp, Wd, bd, di, out);
}